// round 2
// baseline (speedup 1.0000x reference)
#include <cuda_runtime.h>

#define BB    8
#define TT    2000
#define DD    64
#define NRES  2000
#define KPAD  2048
#define SSTR  2052          // padded row stride (floats) -> conflict-free LDS
#define SQ    (SSTR/4)      // 513 float4 per row
#define NBLK  125
#define COLS  16            // 125 * 16 = 2000 exactly, zero waste

// ---------------- device scratch ---------------------------------------------
__device__ float    g_WresT[NRES * SSTR];            // [n][k], k padded to 2048
__device__ float    g_H[(size_t)BB * TT * NRES];     // augmented h
__device__ float    g_S[2 * BB * NRES];              // double-buffered state
__device__ unsigned g_barCnt = 0;
__device__ unsigned g_barGen = 0;

// ---------------- packed f32x2 helpers ---------------------------------------
__device__ __forceinline__ void fma2(unsigned long long& a,
                                     unsigned long long s, unsigned long long w) {
    asm("fma.rn.f32x2 %0, %1, %2, %0;" : "+l"(a) : "l"(s), "l"(w));
}
__device__ __forceinline__ float f2sum(unsigned long long a) {
    float lo, hi;
    asm("mov.b64 {%0, %1}, %2;" : "=f"(lo), "=f"(hi) : "l"(a));
    return lo + hi;
}

// ---------------- software grid barrier --------------------------------------
__device__ __forceinline__ void grid_sync(unsigned nblk) {
    __threadfence();
    __syncthreads();
    if (threadIdx.x == 0) {
        volatile unsigned* genp = &g_barGen;
        unsigned gen = *genp;
        if (atomicInc(&g_barCnt, nblk - 1) == nblk - 1) {
            *genp = gen + 1;
        } else {
            while (*genp == gen) { __nanosleep(32); }
        }
    }
    __syncthreads();
}

// ---------------- Wres -> WresT (padded) -------------------------------------
__global__ void k_transpose(const float* __restrict__ Wres) {
    __shared__ float tile[32][33];
    int tx = threadIdx.x, ty = threadIdx.y;
    int k0 = blockIdx.x * 32;           // 0..2047
    int n0 = blockIdx.y * 32;           // 0..1999
    int k = k0 + ty, n = n0 + tx;
    float v = 0.f;
    if (k < NRES && n < NRES) v = Wres[k * NRES + n];
    tile[ty][tx] = v;
    __syncthreads();
    int nn = n0 + ty, kk = k0 + tx;     // kk < 2048
    if (nn < NRES) g_WresT[(size_t)nn * SSTR + kk] = tile[tx][ty];
}

// ---------------- persistent recurrence kernel -------------------------------
// 256 threads: warp = (cg in 0..1, kq in 0..3); lane = (cs in 0..3, b in 0..7)
// thread owns 2 cols x 1 batch over a 512-wide K-quarter -> no shuffles.
__global__ void __launch_bounds__(256, 1) k_esn(const float* __restrict__ x,
                                                const float* __restrict__ Win) {
    extern __shared__ float smem[];
    float* s_sh = smem;                 // BB * SSTR
    float* w_sh = smem + BB * SSTR;     // COLS * SSTR
    __shared__ float p_sh[4][COLS][BB];
    __shared__ float xs[BB][68];        // stride 68 -> conflict-free
    __shared__ float win_sh[COLS][68];

    const int tid = threadIdx.x;
    const int bid = blockIdx.x;
    const int c0  = bid * COLS;

    // preload WresT slice (once)
    {
        float4*       w4 = (float4*)w_sh;
        const float4* gw = (const float4*)g_WresT;
        for (int i = tid; i < COLS * 512; i += 256) {
            int c = i >> 9, q = i & 511;
            w4[c * SQ + q] = gw[(size_t)(c0 + c) * SQ + q];
        }
    }
    // preload Win slice (once): win_sh[slot][d]
    for (int i = tid; i < COLS * DD; i += 256) {
        int s = i >> 6, d = i & 63;
        win_sh[s][d] = Win[d * NRES + c0 + s];
    }
    // zero state buffer 0
    for (int i = bid * 256 + tid; i < BB * NRES; i += NBLK * 256)
        g_S[i] = 0.f;

    grid_sync(NBLK);

    const int lane = tid & 31, warp = tid >> 5;
    const int cg = warp & 1, kq = warp >> 1;
    const int b  = lane & 7, cs = lane >> 3;
    const int col0 = cg * 8 + cs * 2;

    const ulonglong2* wp0 = (const ulonglong2*)(w_sh + (size_t)col0 * SSTR) + kq * 128;
    const ulonglong2* wp1 = (const ulonglong2*)(w_sh + (size_t)(col0 + 1) * SSTR) + kq * 128;
    const ulonglong2* sp  = (const ulonglong2*)(s_sh + (size_t)b * SSTR) + kq * 128;

    const int f_slot = tid >> 3;        // finalize: tid < 128
    const int f_b    = tid & 7;
    const int f_col  = c0 + f_slot;

    #pragma unroll 1
    for (int t = 0; t < TT; t++) {
        const int buf = t & 1;

        // ---- stage S (L2 -> smem, zero-padded) ----
        {
            const float* Sp = g_S + buf * (BB * NRES);
            #pragma unroll
            for (int bb = 0; bb < BB; bb++) {
                float4*       dst = (float4*)(s_sh + (size_t)bb * SSTR);
                const float4* src = (const float4*)(Sp + bb * NRES);
                for (int q = tid; q < 512; q += 256) {
                    float4 v = make_float4(0.f, 0.f, 0.f, 0.f);
                    if (q < 500) v = __ldcg(src + q);
                    dst[q] = v;
                }
            }
        }
        // ---- stage x row for input projection ----
        if (tid < 128) {
            int xb = tid >> 4, xq = tid & 15;
            float4 v = __ldg((const float4*)(x + ((size_t)xb * TT + t) * DD) + xq);
            *(float4*)&xs[xb][xq * 4] = v;
        }
        __syncthreads();

        // ---- GEMM: 2 cols x 1 batch per thread, packed f32x2 over k --------
        unsigned long long a0 = 0ull, a1 = 0ull, d0 = 0ull, d1 = 0ull;
        #pragma unroll 4
        for (int q = 0; q < 128; q++) {
            ulonglong2 s2  = sp[q];
            ulonglong2 w02 = wp0[q];
            ulonglong2 w12 = wp1[q];
            fma2(a0, s2.x, w02.x);
            fma2(a1, s2.y, w02.y);
            fma2(d0, s2.x, w12.x);
            fma2(d1, s2.y, w12.y);
        }
        p_sh[kq][col0][b]     = f2sum(a0) + f2sum(a1);
        p_sh[kq][col0 + 1][b] = f2sum(d0) + f2sum(d1);
        __syncthreads();

        // ---- finalize: u = x.Win, combine partials, tanh, publish ----------
        if (tid < 128) {
            float u0 = 0.f, u1 = 0.f, u2 = 0.f, u3 = 0.f;
            #pragma unroll
            for (int d = 0; d < DD; d += 4) {
                float4 xv = *(const float4*)&xs[f_b][d];
                float4 wv = *(const float4*)&win_sh[f_slot][d];
                u0 = fmaf(xv.x, wv.x, u0);
                u1 = fmaf(xv.y, wv.y, u1);
                u2 = fmaf(xv.z, wv.z, u2);
                u3 = fmaf(xv.w, wv.w, u3);
            }
            float v = p_sh[0][f_slot][f_b] + p_sh[1][f_slot][f_b]
                    + p_sh[2][f_slot][f_b] + p_sh[3][f_slot][f_b]
                    + (u0 + u1) + (u2 + u3);
            float h = tanhf(v);
            __stcg(&g_S[(buf ^ 1) * (BB * NRES) + f_b * NRES + f_col], h);
            float ha = ((f_col & 1) == 0) ? h * h : h;     // pre-augment
            g_H[((size_t)f_b * TT + t) * NRES + f_col] = ha;
        }

        grid_sync(NBLK);
    }
}

// ---------------- readout: out[b][t][d] = Haug[b][t][:] @ Wout ---------------
#define OT   16
#define HSTR 2004
__global__ void __launch_bounds__(256, 1) k_out(const float* __restrict__ Wout,
                                                float* __restrict__ out) {
    extern __shared__ float hs[];            // [OT][HSTR]
    __shared__ float ps[4][64][OT];
    const int tid = threadIdx.x;
    const int b   = blockIdx.y;
    const int t0  = blockIdx.x * OT;

    for (int r = 0; r < OT; r++) {
        const float4* src = (const float4*)(g_H + ((size_t)b * TT + (t0 + r)) * NRES);
        float4*       dst = (float4*)(hs + r * HSTR);
        for (int i = tid; i < 500; i += 256) dst[i] = __ldg(src + i);
    }
    __syncthreads();

    const int d  = tid & 63;
    const int nq = tid >> 6;                 // 0..3
    float acc[OT];
    #pragma unroll
    for (int r = 0; r < OT; r++) acc[r] = 0.f;

    for (int q = nq; q < 500; q += 4) {
        const int n = q * 4;
        const float w0 = __ldg(&Wout[(size_t)(n + 0) * DD + d]);
        const float w1 = __ldg(&Wout[(size_t)(n + 1) * DD + d]);
        const float w2 = __ldg(&Wout[(size_t)(n + 2) * DD + d]);
        const float w3 = __ldg(&Wout[(size_t)(n + 3) * DD + d]);
        #pragma unroll
        for (int r = 0; r < OT; r++) {
            const float4 h4 = *(const float4*)(hs + r * HSTR + n);
            acc[r] = fmaf(h4.x, w0, acc[r]);
            acc[r] = fmaf(h4.y, w1, acc[r]);
            acc[r] = fmaf(h4.z, w2, acc[r]);
            acc[r] = fmaf(h4.w, w3, acc[r]);
        }
    }
    #pragma unroll
    for (int r = 0; r < OT; r++) ps[nq][d][r] = acc[r];
    __syncthreads();

    for (int i = tid; i < 64 * OT; i += 256) {
        int dd = i >> 4, rr = i & (OT - 1);
        float v = ps[0][dd][rr] + ps[1][dd][rr] + ps[2][dd][rr] + ps[3][dd][rr];
        out[((size_t)b * TT + (t0 + rr)) * DD + dd] = v;
    }
}

// ---------------- launch ------------------------------------------------------
extern "C" void kernel_launch(void* const* d_in, const int* in_sizes, int n_in,
                              void* d_out, int out_size) {
    const float* x    = (const float*)d_in[0];
    const float* Win  = (const float*)d_in[1];
    const float* Wres = (const float*)d_in[2];
    const float* Wout = (const float*)d_in[3];
    float*       out  = (float*)d_out;

    const size_t smem_main = (size_t)(BB + COLS) * SSTR * sizeof(float);   // ~197 KB
    cudaFuncSetAttribute(k_esn, cudaFuncAttributeMaxDynamicSharedMemorySize, (int)smem_main);
    const size_t smem_out = (size_t)OT * HSTR * sizeof(float);             // ~128 KB
    cudaFuncSetAttribute(k_out, cudaFuncAttributeMaxDynamicSharedMemorySize, (int)smem_out);

    k_transpose<<<dim3(KPAD / 32, (NRES + 31) / 32), dim3(32, 32)>>>(Wres);
    k_esn<<<NBLK, 256, smem_main>>>(x, Win);
    k_out<<<dim3(TT / OT, BB), 256, smem_out>>>(Wout, out);
}

// round 4
// speedup vs baseline: 1.1847x; 1.1847x over previous
#include <cuda_runtime.h>

#define BB    8
#define TT    2000
#define DD    64
#define NRES  2000
#define KPAD  2048
#define SSTR  2052          // padded row stride (floats), 16B-aligned
#define NBLK  125
#define COLS  16            // 125 * 16 = 2000 exactly

// ---------------- device scratch ---------------------------------------------
__device__ float    g_WresT[NRES * SSTR];            // [n][k], k zero-padded
__device__ float    g_H[(size_t)BB * TT * NRES];     // augmented h
__device__ float    g_S[2 * BB * NRES];              // double-buffered state
__device__ unsigned g_barCnt = 0;
__device__ unsigned g_barGen = 0;

// ---------------- software grid barrier (proven round-1 version) -------------
__device__ __forceinline__ void grid_sync(unsigned nblk) {
    __threadfence();
    __syncthreads();
    if (threadIdx.x == 0) {
        volatile unsigned* genp = &g_barGen;
        unsigned gen = *genp;
        if (atomicInc(&g_barCnt, nblk - 1) == nblk - 1) {
            *genp = gen + 1;
        } else {
            while (*genp == gen) { __nanosleep(32); }
        }
    }
    __syncthreads();
}

// ---------------- Wres -> WresT (padded) -------------------------------------
__global__ void k_transpose(const float* __restrict__ Wres) {
    __shared__ float tile[32][33];
    int tx = threadIdx.x, ty = threadIdx.y;
    int k0 = blockIdx.x * 32;           // 0..2047
    int n0 = blockIdx.y * 32;           // 0..1999
    int k = k0 + ty, n = n0 + tx;
    float v = 0.f;
    if (k < NRES && n < NRES) v = Wres[k * NRES + n];
    tile[ty][tx] = v;
    __syncthreads();
    int nn = n0 + ty, kk = k0 + tx;
    if (nn < NRES) g_WresT[(size_t)nn * SSTR + kk] = tile[tx][ty];
}

// ---------------- persistent recurrence kernel -------------------------------
// 256 threads. warp = k-slice ks (0..7, 256 floats each).
// lane: bp = lane>>3 (2 batch rows), cp = lane&7 (2 cols).
// thread computes cols {2cp,2cp+1} x b {2bp,2bp+1} over its k-slice.
// Reduction via p_sh (no shuffles).
__global__ void __launch_bounds__(256, 1) k_esn(const float* __restrict__ x,
                                                const float* __restrict__ Win) {
    extern __shared__ float smem[];
    float* s_sh = smem;                 // BB  * SSTR
    float* w_sh = smem + BB * SSTR;     // COLS* SSTR
    __shared__ float p_sh[8][COLS][BB]; // k-slice partials
    __shared__ float xs[BB][68];
    __shared__ float win_sh[COLS][68];

    const int tid = threadIdx.x;
    const int bid = blockIdx.x;
    const int c0  = bid * COLS;

    // preload WresT slice (once)
    {
        float4*       w4 = (float4*)w_sh;
        const float4* gw = (const float4*)g_WresT;
        for (int i = tid; i < COLS * 512; i += 256) {
            int c = i >> 9, q = i & 511;
            w4[(size_t)c * (SSTR / 4) + q] = gw[(size_t)(c0 + c) * (SSTR / 4) + q];
        }
    }
    // preload Win slice (once)
    for (int i = tid; i < COLS * DD; i += 256) {
        int s = i >> 6, d = i & 63;
        win_sh[s][d] = Win[d * NRES + c0 + s];
    }
    // zero state buffer 0
    for (int i = bid * 256 + tid; i < BB * NRES; i += NBLK * 256)
        g_S[i] = 0.f;

    grid_sync(NBLK);

    const int lane = tid & 31;
    const int ks   = tid >> 5;          // k-slice 0..7
    const int bp   = lane >> 3;         // 0..3
    const int cp   = lane & 7;          // 0..7
    const int colA = 2 * cp, colB = 2 * cp + 1;
    const int rowA = 2 * bp, rowB = 2 * bp + 1;

    const float4* w0p = (const float4*)(w_sh + (size_t)colA * SSTR) + ks * 64;
    const float4* w1p = (const float4*)(w_sh + (size_t)colB * SSTR) + ks * 64;
    const float4* s0p = (const float4*)(s_sh + (size_t)rowA * SSTR) + ks * 64;
    const float4* s1p = (const float4*)(s_sh + (size_t)rowB * SSTR) + ks * 64;

    const int f_slot = tid >> 3;        // finalize: tid < 128
    const int f_b    = tid & 7;
    const int f_col  = c0 + f_slot;

    #pragma unroll 1
    for (int t = 0; t < TT; t++) {
        const int buf = t & 1;

        // ---- stage S (L2 -> smem, zero-padded to 2048) ----
        {
            const float* Sp = g_S + buf * (BB * NRES);
            for (int i = tid; i < BB * 512; i += 256) {
                int bb = i >> 9, q = i & 511;
                float4 v = make_float4(0.f, 0.f, 0.f, 0.f);
                if (q < 500)
                    v = __ldcg((const float4*)(Sp + bb * NRES) + q);
                *(float4*)(s_sh + (size_t)bb * SSTR + q * 4) = v;
            }
        }
        // ---- stage x row ----
        if (tid < 128) {
            int xb = tid >> 4, xq = tid & 15;
            float4 v = __ldg((const float4*)(x + ((size_t)xb * TT + t) * DD) + xq);
            *(float4*)&xs[xb][xq * 4] = v;
        }
        __syncthreads();

        // ---- input projection u (warps 0..3, overlaps others' GEMM) ----
        float ufin = 0.f;
        if (tid < 128) {
            float u0 = 0.f, u1 = 0.f, u2 = 0.f, u3 = 0.f;
            #pragma unroll
            for (int d = 0; d < DD; d += 4) {
                float4 xv = *(const float4*)&xs[f_b][d];
                float4 wv = *(const float4*)&win_sh[f_slot][d];
                u0 = fmaf(xv.x, wv.x, u0);
                u1 = fmaf(xv.y, wv.y, u1);
                u2 = fmaf(xv.z, wv.z, u2);
                u3 = fmaf(xv.w, wv.w, u3);
            }
            ufin = (u0 + u1) + (u2 + u3);
        }

        // ---- GEMM: 2 cols x 2 rows per thread, 16 independent FMA chains ---
        float4 c00 = make_float4(0.f, 0.f, 0.f, 0.f);
        float4 c01 = c00, c10 = c00, c11 = c00;
        #pragma unroll 4
        for (int q = 0; q < 64; q++) {
            const float4 wA = w0p[q];
            const float4 wB = w1p[q];
            const float4 sA = s0p[q];
            const float4 sB = s1p[q];
            c00.x = fmaf(sA.x, wA.x, c00.x);
            c00.y = fmaf(sA.y, wA.y, c00.y);
            c00.z = fmaf(sA.z, wA.z, c00.z);
            c00.w = fmaf(sA.w, wA.w, c00.w);
            c01.x = fmaf(sA.x, wB.x, c01.x);
            c01.y = fmaf(sA.y, wB.y, c01.y);
            c01.z = fmaf(sA.z, wB.z, c01.z);
            c01.w = fmaf(sA.w, wB.w, c01.w);
            c10.x = fmaf(sB.x, wA.x, c10.x);
            c10.y = fmaf(sB.y, wA.y, c10.y);
            c10.z = fmaf(sB.z, wA.z, c10.z);
            c10.w = fmaf(sB.w, wA.w, c10.w);
            c11.x = fmaf(sB.x, wB.x, c11.x);
            c11.y = fmaf(sB.y, wB.y, c11.y);
            c11.z = fmaf(sB.z, wB.z, c11.z);
            c11.w = fmaf(sB.w, wB.w, c11.w);
        }
        p_sh[ks][colA][rowA] = (c00.x + c00.y) + (c00.z + c00.w);
        p_sh[ks][colB][rowA] = (c01.x + c01.y) + (c01.z + c01.w);
        p_sh[ks][colA][rowB] = (c10.x + c10.y) + (c10.z + c10.w);
        p_sh[ks][colB][rowB] = (c11.x + c11.y) + (c11.z + c11.w);
        __syncthreads();

        // ---- finalize ----
        if (tid < 128) {
            float v = ufin;
            #pragma unroll
            for (int k = 0; k < 8; k++) v += p_sh[k][f_slot][f_b];
            float h = tanhf(v);
            __stcg(&g_S[(buf ^ 1) * (BB * NRES) + f_b * NRES + f_col], h);
            float ha = ((f_col & 1) == 0) ? h * h : h;   // pre-augment
            g_H[((size_t)f_b * TT + t) * NRES + f_col] = ha;
        }

        grid_sync(NBLK);
    }
}

// ---------------- readout: out[b][t][d] = Haug[b][t][:] @ Wout ---------------
#define OT   8
#define HSTR 2004
__global__ void __launch_bounds__(256, 2) k_out(const float* __restrict__ Wout,
                                                float* __restrict__ out) {
    extern __shared__ float hs[];            // [OT][HSTR]
    __shared__ float ps[4][64][OT];
    const int tid = threadIdx.x;
    const int b   = blockIdx.y;
    const int t0  = blockIdx.x * OT;

    for (int r = 0; r < OT; r++) {
        const float4* src = (const float4*)(g_H + ((size_t)b * TT + (t0 + r)) * NRES);
        float4*       dst = (float4*)(hs + r * HSTR);
        for (int i = tid; i < 500; i += 256) dst[i] = __ldcg(src + i);
    }
    __syncthreads();

    const int d  = tid & 63;
    const int nq = tid >> 6;                 // 0..3
    float acc[OT];
    #pragma unroll
    for (int r = 0; r < OT; r++) acc[r] = 0.f;

    for (int q = nq; q < 500; q += 4) {
        const int n = q * 4;
        const float w0 = __ldg(&Wout[(size_t)(n + 0) * DD + d]);
        const float w1 = __ldg(&Wout[(size_t)(n + 1) * DD + d]);
        const float w2 = __ldg(&Wout[(size_t)(n + 2) * DD + d]);
        const float w3 = __ldg(&Wout[(size_t)(n + 3) * DD + d]);
        #pragma unroll
        for (int r = 0; r < OT; r++) {
            const float4 h4 = *(const float4*)(hs + r * HSTR + n);
            acc[r] = fmaf(h4.x, w0, acc[r]);
            acc[r] = fmaf(h4.y, w1, acc[r]);
            acc[r] = fmaf(h4.z, w2, acc[r]);
            acc[r] = fmaf(h4.w, w3, acc[r]);
        }
    }
    #pragma unroll
    for (int r = 0; r < OT; r++) ps[nq][d][r] = acc[r];
    __syncthreads();

    for (int i = tid; i < 64 * OT; i += 256) {
        int dd = i >> 3, rr = i & (OT - 1);
        float v = ps[0][dd][rr] + ps[1][dd][rr] + ps[2][dd][rr] + ps[3][dd][rr];
        out[((size_t)b * TT + (t0 + rr)) * DD + dd] = v;
    }
}

// ---------------- launch ------------------------------------------------------
extern "C" void kernel_launch(void* const* d_in, const int* in_sizes, int n_in,
                              void* d_out, int out_size) {
    const float* x    = (const float*)d_in[0];
    const float* Win  = (const float*)d_in[1];
    const float* Wres = (const float*)d_in[2];
    const float* Wout = (const float*)d_in[3];
    float*       out  = (float*)d_out;

    const size_t smem_main = (size_t)(BB + COLS) * SSTR * sizeof(float);   // ~197 KB
    cudaFuncSetAttribute(k_esn, cudaFuncAttributeMaxDynamicSharedMemorySize, (int)smem_main);
    const size_t smem_out = (size_t)OT * HSTR * sizeof(float);             // ~64 KB
    cudaFuncSetAttribute(k_out, cudaFuncAttributeMaxDynamicSharedMemorySize, (int)smem_out);

    k_transpose<<<dim3(KPAD / 32, (NRES + 31) / 32), dim3(32, 32)>>>(Wres);
    k_esn<<<NBLK, 256, smem_main>>>(x, Win);
    k_out<<<dim3(TT / OT, BB), 256, smem_out>>>(Wout, out);
}

// round 5
// speedup vs baseline: 1.5134x; 1.2775x over previous
#include <cuda_runtime.h>

#define BB   8
#define TT   2000
#define DD   64
#define NRES 2000
#define KPAD 2048
#define KQ   (KPAD/4)     // 512 float4 per row
#define MAXC 16           // max column slots per block

// ---------------- device scratch ---------------------------------------------
__device__ float    g_WresT[NRES * KPAD];        // [n][k], k zero-padded (16 MB)
__device__ float    g_U[TT * BB * NRES];         // [t][b][n]              (128 MB)
__device__ float    g_H[BB * TT * NRES];         // [b][t][n]              (128 MB)
__device__ float    g_S[2 * BB * NRES];          // double-buffered state
__device__ unsigned g_barCnt = 0;                // legacy entry barrier
__device__ unsigned g_barGen = 0;
__device__ unsigned g_arrive[256 * 32];          // per-block flag, 128B apart
__device__ unsigned g_release = 0;               // monotone across replays

// ---------------- legacy atomic barrier (entry only; replay-safe) ------------
__device__ __forceinline__ void entry_sync(unsigned nblk) {
    __threadfence();
    __syncthreads();
    if (threadIdx.x == 0) {
        volatile unsigned* genp = &g_barGen;
        unsigned gen = *genp;
        if (atomicInc(&g_barCnt, nblk - 1) == nblk - 1) {
            *genp = gen + 1;
        } else {
            while (*genp == gen) { __nanosleep(64); }
        }
    }
    __syncthreads();
}

// ---------------- fast distributed-flag barrier ------------------------------
// arrive: one padded STG per block (parallel). block 0 aggregates, releases.
__device__ __forceinline__ void fast_sync(int nblk, int bid, unsigned gen) {
    __threadfence();          // order g_S/g_H writes before the flag
    __syncthreads();
    if (threadIdx.x == 0)
        *(volatile unsigned*)&g_arrive[bid * 32] = gen;
    if (bid == 0) {
        if ((int)threadIdx.x < nblk) {
            volatile unsigned* f = &g_arrive[threadIdx.x * 32];
            while (*f < gen) { }
        }
        __syncthreads();      // all flags seen
        if (threadIdx.x == 0) {
            __threadfence();
            *(volatile unsigned*)&g_release = gen;
        }
        __syncthreads();
    } else {
        if (threadIdx.x == 0) {
            volatile unsigned* r = &g_release;
            while (*r < gen) { }
        }
        __syncthreads();
    }
}

// ---------------- Wres -> WresT (padded) -------------------------------------
__global__ void k_transpose(const float* __restrict__ Wres) {
    __shared__ float tile[32][33];
    int tx = threadIdx.x, ty = threadIdx.y;
    int k0 = blockIdx.x * 32;           // k tile (0..2047)
    int n0 = blockIdx.y * 32;           // n tile (0..1999)
    int k = k0 + ty, n = n0 + tx;
    float v = 0.f;
    if (k < NRES && n < NRES) v = Wres[k * NRES + n];
    tile[ty][tx] = v;
    __syncthreads();
    int nn = n0 + ty, kk = k0 + tx;
    if (nn < NRES) g_WresT[nn * KPAD + kk] = tile[tx][ty];
}

// ---------------- U[t][b][n] = sum_d x[b][t][d] * Win[d][n] ------------------
__global__ void k_u(const float* __restrict__ x, const float* __restrict__ Win) {
    __shared__ float xs[BB][DD];
    int t = blockIdx.x, tid = threadIdx.x;
    if (tid < BB * (DD / 4)) {
        int b = tid / (DD / 4), q = tid % (DD / 4);
        ((float4*)&xs[b][0])[q] = ((const float4*)(x + (size_t)(b * TT + t) * DD))[q];
    }
    __syncthreads();
    for (int n = tid; n < NRES; n += blockDim.x) {
        float acc[BB];
        #pragma unroll
        for (int b = 0; b < BB; b++) acc[b] = 0.f;
        #pragma unroll
        for (int d4 = 0; d4 < DD / 4; d4++) {
            float w0 = Win[(d4 * 4 + 0) * NRES + n];
            float w1 = Win[(d4 * 4 + 1) * NRES + n];
            float w2 = Win[(d4 * 4 + 2) * NRES + n];
            float w3 = Win[(d4 * 4 + 3) * NRES + n];
            #pragma unroll
            for (int b = 0; b < BB; b++) {
                float4 xv = *(const float4*)&xs[b][d4 * 4];
                acc[b] = fmaf(xv.x, w0, acc[b]);
                acc[b] = fmaf(xv.y, w1, acc[b]);
                acc[b] = fmaf(xv.z, w2, acc[b]);
                acc[b] = fmaf(xv.w, w3, acc[b]);
            }
        }
        #pragma unroll
        for (int b = 0; b < BB; b++) g_U[(size_t)(t * BB + b) * NRES + n] = acc[b];
    }
}

// ---------------- persistent recurrence kernel (round-1 proven layout) -------
__global__ void __launch_bounds__(256, 1) k_esn() {
    extern __shared__ float smem[];
    float* s_sh = smem;                 // BB * KPAD
    float* w_sh = smem + BB * KPAD;     // MAXC * KPAD
    __shared__ float p_sh[2][MAXC][BB]; // k-half partials

    const int tid  = threadIdx.x;
    const int lane = tid & 31;
    const int warp = tid >> 5;
    const int nblk = gridDim.x;
    const int bid  = blockIdx.x;

    const int base = NRES / nblk, rem = NRES % nblk;
    const int c0    = bid * base + (bid < rem ? bid : rem);
    const int ncols = base + (bid < rem ? 1 : 0);   // <= 16

    // preload this block's WresT slice into smem (once)
    {
        float4*       w4  = (float4*)w_sh;
        const float4* gW4 = (const float4*)g_WresT;
        for (int i = tid; i < MAXC * KQ; i += blockDim.x) {
            int c = i >> 9;
            int q = i & (KQ - 1);
            float4 v = make_float4(0.f, 0.f, 0.f, 0.f);
            if (c < ncols) v = gW4[(size_t)(c0 + c) * KQ + q];
            w4[i] = v;
        }
    }

    // zero state buffer 0 (grid-strided)
    for (int i = bid * blockDim.x + tid; i < BB * NRES; i += nblk * blockDim.x)
        g_S[i] = 0.f;

    entry_sync(nblk);
    // launch-consistent generation base (monotone across graph replays)
    const unsigned genbase = *(volatile unsigned*)&g_release;

    const int kh = warp >> 2;           // K-half: 0 or 1
    const int cs = warp & 3;            // column-slot group: 4 cols each

    const int  f_slot = tid >> 3;       // finalize: tid < 128
    const int  f_b    = tid & 7;
    const bool f_act  = (tid < MAXC * BB) && (f_slot < ncols);
    const int  f_col  = c0 + f_slot;

    const float4* wr0 = (const float4*)w_sh + (size_t)(cs * 4 + 0) * KQ;
    const float4* wr1 = (const float4*)w_sh + (size_t)(cs * 4 + 1) * KQ;
    const float4* wr2 = (const float4*)w_sh + (size_t)(cs * 4 + 2) * KQ;
    const float4* wr3 = (const float4*)w_sh + (size_t)(cs * 4 + 3) * KQ;
    const float4* sB  = (const float4*)s_sh;

    #pragma unroll 1
    for (int t = 0; t < TT; t++) {
        const int buf = t & 1;

        // prefetch this step's input-projection value
        float uval = 0.f;
        if (f_act) uval = __ldg(&g_U[(size_t)(t * BB + f_b) * NRES + f_col]);

        // stage S (L2) -> smem, zero-padded to 2048
        {
            const float* Sp = g_S + (size_t)buf * (BB * NRES);
            float4* s4 = (float4*)s_sh;
            for (int i = tid; i < BB * KQ; i += blockDim.x) {
                int b = i >> 9;
                int q = i & (KQ - 1);
                float4 v = make_float4(0.f, 0.f, 0.f, 0.f);
                if (q * 4 < NRES)
                    v = __ldcg((const float4*)(Sp + (size_t)b * NRES + q * 4));
                s4[(size_t)b * KQ + q] = v;
            }
        }
        __syncthreads();

        // 4 cols x 8 batch rows per warp, over this warp's K-half
        float acc[4][8];
        #pragma unroll
        for (int c = 0; c < 4; c++)
            #pragma unroll
            for (int b = 0; b < 8; b++) acc[c][b] = 0.f;

        #pragma unroll
        for (int it = 0; it < 8; it++) {
            const int kq = kh * 256 + it * 32 + lane;
            const float4 w0 = wr0[kq];
            const float4 w1 = wr1[kq];
            const float4 w2 = wr2[kq];
            const float4 w3 = wr3[kq];
            #pragma unroll
            for (int b = 0; b < 8; b++) {
                const float4 s = sB[(size_t)b * KQ + kq];
                acc[0][b] = fmaf(s.x, w0.x, acc[0][b]);
                acc[0][b] = fmaf(s.y, w0.y, acc[0][b]);
                acc[0][b] = fmaf(s.z, w0.z, acc[0][b]);
                acc[0][b] = fmaf(s.w, w0.w, acc[0][b]);
                acc[1][b] = fmaf(s.x, w1.x, acc[1][b]);
                acc[1][b] = fmaf(s.y, w1.y, acc[1][b]);
                acc[1][b] = fmaf(s.z, w1.z, acc[1][b]);
                acc[1][b] = fmaf(s.w, w1.w, acc[1][b]);
                acc[2][b] = fmaf(s.x, w2.x, acc[2][b]);
                acc[2][b] = fmaf(s.y, w2.y, acc[2][b]);
                acc[2][b] = fmaf(s.z, w2.z, acc[2][b]);
                acc[2][b] = fmaf(s.w, w2.w, acc[2][b]);
                acc[3][b] = fmaf(s.x, w3.x, acc[3][b]);
                acc[3][b] = fmaf(s.y, w3.y, acc[3][b]);
                acc[3][b] = fmaf(s.z, w3.z, acc[3][b]);
                acc[3][b] = fmaf(s.w, w3.w, acc[3][b]);
            }
        }

        // warp reduction
        #pragma unroll
        for (int c = 0; c < 4; c++)
            #pragma unroll
            for (int b = 0; b < 8; b++) {
                float v = acc[c][b];
                v += __shfl_xor_sync(0xFFFFFFFFu, v, 16);
                v += __shfl_xor_sync(0xFFFFFFFFu, v, 8);
                v += __shfl_xor_sync(0xFFFFFFFFu, v, 4);
                v += __shfl_xor_sync(0xFFFFFFFFu, v, 2);
                v += __shfl_xor_sync(0xFFFFFFFFu, v, 1);
                acc[c][b] = v;
            }
        if (lane == 0) {
            #pragma unroll
            for (int c = 0; c < 4; c++)
                #pragma unroll
                for (int b = 0; b < 8; b++)
                    p_sh[kh][cs * 4 + c][b] = acc[c][b];
        }
        __syncthreads();

        if (f_act) {
            float v = p_sh[0][f_slot][f_b] + p_sh[1][f_slot][f_b] + uval;
            float h = tanhf(v);
            const int nbuf = buf ^ 1;
            __stcg(&g_S[(size_t)nbuf * (BB * NRES) + (size_t)f_b * NRES + f_col], h);
            float ha = ((f_col & 1) == 0) ? h * h : h;   // pre-augment for k_out
            g_H[((size_t)f_b * TT + t) * NRES + f_col] = ha;
        }

        fast_sync(nblk, bid, genbase + 1 + t);
    }
}

// ---------------- readout: out[b][t][d] = Haug[b][t][:] @ Wout ---------------
#define OT   8
#define HSTR 2004
__global__ void __launch_bounds__(256, 2) k_out(const float* __restrict__ Wout,
                                                float* __restrict__ out) {
    extern __shared__ float hs[];            // [OT][HSTR]
    __shared__ float ps[4][64][OT];
    const int tid = threadIdx.x;
    const int b   = blockIdx.y;
    const int t0  = blockIdx.x * OT;

    for (int r = 0; r < OT; r++) {
        const float4* src = (const float4*)(g_H + ((size_t)b * TT + (t0 + r)) * NRES);
        float4*       dst = (float4*)(hs + r * HSTR);
        for (int i = tid; i < 500; i += 256) dst[i] = __ldcg(src + i);
    }
    __syncthreads();

    const int d  = tid & 63;
    const int nq = tid >> 6;                 // 0..3
    float acc[OT];
    #pragma unroll
    for (int r = 0; r < OT; r++) acc[r] = 0.f;

    for (int q = nq; q < 500; q += 4) {
        const int n = q * 4;
        const float w0 = __ldg(&Wout[(size_t)(n + 0) * DD + d]);
        const float w1 = __ldg(&Wout[(size_t)(n + 1) * DD + d]);
        const float w2 = __ldg(&Wout[(size_t)(n + 2) * DD + d]);
        const float w3 = __ldg(&Wout[(size_t)(n + 3) * DD + d]);
        #pragma unroll
        for (int r = 0; r < OT; r++) {
            const float4 h4 = *(const float4*)(hs + r * HSTR + n);
            acc[r] = fmaf(h4.x, w0, acc[r]);
            acc[r] = fmaf(h4.y, w1, acc[r]);
            acc[r] = fmaf(h4.z, w2, acc[r]);
            acc[r] = fmaf(h4.w, w3, acc[r]);
        }
    }
    #pragma unroll
    for (int r = 0; r < OT; r++) ps[nq][d][r] = acc[r];
    __syncthreads();

    for (int i = tid; i < 64 * OT; i += 256) {
        int dd = i >> 3, rr = i & (OT - 1);
        float v = ps[0][dd][rr] + ps[1][dd][rr] + ps[2][dd][rr] + ps[3][dd][rr];
        out[((size_t)b * TT + (t0 + rr)) * DD + dd] = v;
    }
}

// ---------------- launch ------------------------------------------------------
extern "C" void kernel_launch(void* const* d_in, const int* in_sizes, int n_in,
                              void* d_out, int out_size) {
    const float* x    = (const float*)d_in[0];
    const float* Win  = (const float*)d_in[1];
    const float* Wres = (const float*)d_in[2];
    const float* Wout = (const float*)d_in[3];
    float*       out  = (float*)d_out;

    int dev = 0;
    cudaGetDevice(&dev);
    int nsm = 148;
    cudaDeviceGetAttribute(&nsm, cudaDevAttrMultiProcessorCount, dev);
    int nblk = nsm < 148 ? nsm : 148;   // 1 block/SM, all resident
    if (nblk < 125) nblk = 125;         // column-slot capacity guard (16/block)

    const size_t smem_main = (size_t)(BB * KPAD + MAXC * KPAD) * sizeof(float); // 192 KB
    cudaFuncSetAttribute(k_esn, cudaFuncAttributeMaxDynamicSharedMemorySize, (int)smem_main);
    const size_t smem_out = (size_t)OT * HSTR * sizeof(float);                  // ~64 KB
    cudaFuncSetAttribute(k_out, cudaFuncAttributeMaxDynamicSharedMemorySize, (int)smem_out);

    k_transpose<<<dim3(KPAD / 32, (NRES + 31) / 32), dim3(32, 32)>>>(Wres);
    k_u<<<TT, 256>>>(x, Win);
    k_esn<<<nblk, 256, smem_main>>>();
    k_out<<<dim3(TT / OT, BB), 256, smem_out>>>(Wout, out);
}